// round 3
// baseline (speedup 1.0000x reference)
#include <cuda_runtime.h>
#include <math.h>

#define LL 4096
#define FF 36
#define MM 100
#define HID 64
#define NEG_INF_V (-1e9f)

#define NCH 32
#define CHROWS 128   // NCH*CHROWS == LL

// ---------------- device scratch (no allocations allowed) ----------------
__device__ __align__(128) float g_S [(LL + 1) * FF];   // prefix sums, row-major (L+1, F)
__device__ __align__(128) float g_S2[(LL + 1) * FF];   // prefix sums of squares
__device__ float  g_partS [NCH * FF];
__device__ float  g_partS2[NCH * FF];
__device__ float  g_kc;                 // c * log2(e)
__device__ float4 g_ltab[MM];           // (1/l, l/500, log(l+1e-6)/6, 0)
__device__ float  g_bp[HID];            // sorted relu breakpoints
__device__ float2 g_ab[HID + 1];        // (slope, intercept) per bin

__device__ __forceinline__ float ex2(float x) {
    float y;
    asm("ex2.approx.ftz.f32 %0, %1;" : "=f"(y) : "f"(x));
    return y;
}

// ---------------- prep: scalar temperature, l-tables, piecewise-linear MLP ----------------
__global__ void k_prep(const float* __restrict__ wf, const float* __restrict__ q,
                       const float* __restrict__ w1, const float* __restrict__ b1,
                       const float* __restrict__ w2, const float* __restrict__ b2) {
    __shared__ float sv[HID];
    __shared__ float stb[HID], sdA[HID], sdB[HID];
    int t = threadIdx.x;
    if (t < HID) {
        float acc = 0.f;
        #pragma unroll
        for (int a = 0; a < 32; a++) acc = fmaf(wf[a], w1[a * HID + t], acc);
        sv[t] = acc;
    }
    if (t == 0) {
        float c = 0.f;
        #pragma unroll
        for (int a = 0; a < 32; a++) c = fmaf(wf[a], q[a], c);
        g_kc = c * 1.4426950408889634f;
    }
    if (t < MM) {
        float lf = (float)(t + 1);
        float4 v;
        v.x = 1.0f / lf;
        v.y = lf * (1.0f / 500.0f);
        v.z = logf(lf + 1e-6f) * (1.0f / 6.0f);
        v.w = 0.f;
        g_ltab[t] = v;
    }
    __syncthreads();
    if (t == 0) {
        float A0 = 0.f, B0 = b2[0];
        for (int h = 0; h < HID; h++) {
            float vh = sv[h], bh = b1[h], wh = w2[h];
            if (vh > 0.f)      { stb[h] = -bh / vh; sdA[h] =  wh * vh; sdB[h] =  wh * bh; }
            else if (vh < 0.f) { stb[h] = -bh / vh; sdA[h] = -wh * vh; sdB[h] = -wh * bh;
                                 A0 += wh * vh; B0 += wh * bh; }
            else               { stb[h] = 3e38f; sdA[h] = 0.f; sdB[h] = 0.f;
                                 B0 += wh * fmaxf(bh, 0.f); }
        }
        // insertion sort by breakpoint
        for (int a = 1; a < HID; a++) {
            float tb = stb[a], da = sdA[a], db = sdB[a];
            int b = a - 1;
            while (b >= 0 && stb[b] > tb) {
                stb[b + 1] = stb[b]; sdA[b + 1] = sdA[b]; sdB[b + 1] = sdB[b]; b--;
            }
            stb[b + 1] = tb; sdA[b + 1] = da; sdB[b + 1] = db;
        }
        float A = A0, B = B0;
        g_ab[0] = make_float2(A, B);
        for (int j = 0; j < HID; j++) {
            g_bp[j] = stb[j];
            A += sdA[j]; B += sdB[j];
            g_ab[j + 1] = make_float2(A, B);
        }
    }
}

// ---------------- chunked prefix scan: partials -> offsets -> write ----------------
__global__ void k_part(const float* __restrict__ x) {
    int t = blockIdx.x * blockDim.x + threadIdx.x;
    if (t >= NCH * FF) return;
    int f = t % FF, ch = t / FF;
    const float* p = x + (size_t)ch * CHROWS * FF + f;
    float s = 0.f, s2 = 0.f;
    #pragma unroll 4
    for (int r = 0; r < CHROWS; r++) {
        float v = p[r * FF];
        s += v; s2 = fmaf(v, v, s2);
    }
    g_partS[t] = s; g_partS2[t] = s2;
}

__global__ void k_off() {
    int f = threadIdx.x;
    if (f >= FF) return;
    float s = 0.f, s2 = 0.f;
    for (int ch = 0; ch < NCH; ch++) {
        int idx = ch * FF + f;
        float a = g_partS[idx], b = g_partS2[idx];
        g_partS[idx] = s; g_partS2[idx] = s2;   // exclusive
        s += a; s2 += b;
    }
}

__global__ void k_scan(const float* __restrict__ x) {
    int t = blockIdx.x * blockDim.x + threadIdx.x;
    if (t >= NCH * FF) return;
    int f = t % FF, ch = t / FF;
    float s = g_partS[t], s2 = g_partS2[t];
    if (ch == 0) { g_S[f] = 0.f; g_S2[f] = 0.f; }
    const float* p = x + (size_t)ch * CHROWS * FF + f;
    float* oS  = g_S  + ((size_t)ch * CHROWS + 1) * FF + f;
    float* oS2 = g_S2 + ((size_t)ch * CHROWS + 1) * FF + f;
    for (int r = 0; r < CHROWS; r++) {
        float v = p[r * FF];
        s += v; s2 = fmaf(v, v, s2);
        oS[r * FF] = s; oS2[r * FF] = s2;
    }
}

// ---------------- main: one thread per (i, l) cell ----------------
__global__ __launch_bounds__(256) void k_main(float* __restrict__ out) {
    __shared__ float4 s_lt[MM];
    __shared__ float  s_bp[HID];
    __shared__ float2 s_ab[HID + 1];
    __shared__ float  s_kc;
    int t = threadIdx.x;
    if (t < MM)       s_lt[t] = g_ltab[t];
    if (t < HID)      s_bp[t] = g_bp[t];
    if (t < HID + 1)  s_ab[t] = g_ab[t];
    if (t == 0)       s_kc = g_kc;
    __syncthreads();

    int g = blockIdx.x * 256 + t;
    if (g >= LL * MM) return;
    int i   = g / MM;
    int lm1 = g - i * MM;
    int l   = lm1 + 1;
    if (i + l > LL) { out[g] = NEG_INF_V; return; }

    float4 lt  = s_lt[lm1];
    float invl = lt.x, lenf = lt.y, llf = lt.z;

    const float4* pSi = (const float4*)(g_S  + (size_t)i * FF);
    const float4* pSe = (const float4*)(g_S  + (size_t)(i + l) * FF);
    const float4* pQi = (const float4*)(g_S2 + (size_t)i * FF);
    const float4* pQe = (const float4*)(g_S2 + (size_t)(i + l) * FF);

    float am[FF], av[FF];
    float amax = fmaxf(lenf, llf);
    float amin = fminf(lenf, llf);

    #pragma unroll
    for (int j = 0; j < 9; j++) {
        float4 a = pSe[j], b = pSi[j], c = pQe[j], d = pQi[j];
        {
            float m = (a.x - b.x) * invl; float vv = fmaf(c.x - d.x, invl, -(m * m));
            am[4*j+0] = m; av[4*j+0] = vv;
            amax = fmaxf(amax, fmaxf(m, vv)); amin = fminf(amin, fminf(m, vv));
        }
        {
            float m = (a.y - b.y) * invl; float vv = fmaf(c.y - d.y, invl, -(m * m));
            am[4*j+1] = m; av[4*j+1] = vv;
            amax = fmaxf(amax, fmaxf(m, vv)); amin = fminf(amin, fminf(m, vv));
        }
        {
            float m = (a.z - b.z) * invl; float vv = fmaf(c.z - d.z, invl, -(m * m));
            am[4*j+2] = m; av[4*j+2] = vv;
            amax = fmaxf(amax, fmaxf(m, vv)); amin = fminf(amin, fminf(m, vv));
        }
        {
            float m = (a.w - b.w) * invl; float vv = fmaf(c.w - d.w, invl, -(m * m));
            am[4*j+3] = m; av[4*j+3] = vv;
            amax = fmaxf(amax, fmaxf(m, vv)); amin = fminf(amin, fminf(m, vv));
        }
    }

    float kc = s_kc;
    float mz = (kc >= 0.f ? amax : amin) * kc;   // max over d of kc*agg_d

    float den0 = 0.f, den1 = 0.f, num0 = 0.f, num1 = 0.f;
    #pragma unroll
    for (int f = 0; f < FF; f++) {
        float a = am[f]; float e  = ex2(fmaf(a, kc, -mz)); den0 += e;  num0 = fmaf(a, e,  num0);
        float b = av[f]; float e2 = ex2(fmaf(b, kc, -mz)); den1 += e2; num1 = fmaf(b, e2, num1);
    }
    { float e = ex2(fmaf(lenf, kc, -mz)); den0 += e; num0 = fmaf(lenf, e, num0); }
    { float e = ex2(fmaf(llf,  kc, -mz)); den1 += e; num1 = fmaf(llf,  e, num1); }

    float s = __fdividef(num0 + num1, den0 + den1);

    // rank of s among sorted breakpoints (branchless, 7 steps covers 0..64)
    int lo = 0;
    #pragma unroll
    for (int st = 64; st > 0; st >>= 1) {
        int nx = lo + st;
        if (nx <= HID && s >= s_bp[nx - 1]) lo = nx;
    }
    float2 ab = s_ab[lo];
    out[g] = fmaf(ab.x, s, ab.y);
}

// ---------------- launch ----------------
extern "C" void kernel_launch(void* const* d_in, const int* in_sizes, int n_in,
                              void* d_out, int out_size) {
    const float* x  = (const float*)d_in[0];
    const float* wf = (const float*)d_in[1];
    const float* q  = (const float*)d_in[2];
    const float* w1 = (const float*)d_in[3];
    const float* b1 = (const float*)d_in[4];
    const float* w2 = (const float*)d_in[5];
    const float* b2 = (const float*)d_in[6];
    float* out = (float*)d_out;

    k_prep<<<1, 128>>>(wf, q, w1, b1, w2, b2);
    k_part<<<(NCH * FF + 127) / 128, 128>>>(x);
    k_off <<<1, 64>>>();
    k_scan<<<(NCH * FF + 127) / 128, 128>>>(x);
    k_main<<<(LL * MM) / 256, 256>>>(out);
}

// round 4
// speedup vs baseline: 1.1223x; 1.1223x over previous
#include <cuda_runtime.h>
#include <math.h>

#define LL 4096
#define FF 36
#define MM 100
#define HID 64
#define NEG_INF_V (-1e9f)

#define NCH 128
#define CHROWS 32   // NCH*CHROWS == LL

typedef unsigned long long u64;

// ---------------- device scratch ----------------
// interleaved prefix sums: g_P[row*72 + 2f] = S, g_P[row*72 + 2f + 1] = S2
__device__ __align__(128) float g_P[(LL + 1) * 2 * FF];
__device__ float  g_partS [NCH * FF];
__device__ float  g_partS2[NCH * FF];
__device__ float  g_kc;                 // c * log2(e)
__device__ float4 g_ltab[MM];           // (1/l, l/500, log(l+1e-6)/6, 0)
__device__ float  g_bp[HID];            // sorted relu breakpoints
__device__ float2 g_ab[HID + 1];        // (slope, intercept) per bin

// ---------------- f32x2 packed helpers (sm_100) ----------------
__device__ __forceinline__ float ex2(float x) {
    float y; asm("ex2.approx.ftz.f32 %0, %1;" : "=f"(y) : "f"(x)); return y;
}
__device__ __forceinline__ u64 pk(float lo, float hi) {
    u64 r; asm("mov.b64 %0, {%1,%2};" : "=l"(r) : "f"(lo), "f"(hi)); return r;
}
__device__ __forceinline__ void upk(u64 v, float& lo, float& hi) {
    asm("mov.b64 {%0,%1}, %2;" : "=f"(lo), "=f"(hi) : "l"(v));
}
__device__ __forceinline__ u64 fma2(u64 a, u64 b, u64 c) {
    u64 d; asm("fma.rn.f32x2 %0, %1, %2, %3;" : "=l"(d) : "l"(a), "l"(b), "l"(c)); return d;
}
__device__ __forceinline__ u64 add2(u64 a, u64 b) {
    u64 d; asm("add.rn.f32x2 %0, %1, %2;" : "=l"(d) : "l"(a), "l"(b)); return d;
}
__device__ __forceinline__ u64 mul2(u64 a, u64 b) {
    u64 d; asm("mul.rn.f32x2 %0, %1, %2;" : "=l"(d) : "l"(a), "l"(b)); return d;
}

// ---------------- chunk partials ----------------
__global__ void k_part(const float* __restrict__ x) {
    int t = blockIdx.x * blockDim.x + threadIdx.x;
    if (t >= NCH * FF) return;
    int f = t % FF, ch = t / FF;
    const float* p = x + (size_t)ch * CHROWS * FF + f;
    float s = 0.f, s2 = 0.f;
    #pragma unroll 8
    for (int r = 0; r < CHROWS; r++) {
        float v = p[r * FF];
        s += v; s2 = fmaf(v, v, s2);
    }
    g_partS[t] = s; g_partS2[t] = s2;
}

// ---------------- merged prep (MLP collapse) + chunk-offset scan ----------------
__global__ void k_prep_off(const float* __restrict__ wf, const float* __restrict__ q,
                           const float* __restrict__ w1, const float* __restrict__ b1,
                           const float* __restrict__ w2, const float* __restrict__ b2) {
    __shared__ float sv[HID];
    __shared__ float stb[HID], sdA[HID], sdB[HID];
    __shared__ float shS[NCH * FF], shS2[NCH * FF];
    int t = threadIdx.x;

    // --- load partials to shared ---
    for (int idx = t; idx < NCH * FF; idx += blockDim.x) {
        shS[idx] = g_partS[idx]; shS2[idx] = g_partS2[idx];
    }

    // --- prep: v = wf @ w1, c = wf . q, l tables ---
    if (t < HID) {
        float acc = 0.f;
        #pragma unroll
        for (int a = 0; a < 32; a++) acc = fmaf(wf[a], w1[a * HID + t], acc);
        sv[t] = acc;
    }
    if (t == 0) {
        float c = 0.f;
        #pragma unroll
        for (int a = 0; a < 32; a++) c = fmaf(wf[a], q[a], c);
        g_kc = c * 1.4426950408889634f;
    }
    if (t < MM) {
        float lf = (float)(t + 1);
        float4 v;
        v.x = 1.0f / lf;
        v.y = lf * (1.0f / 500.0f);
        v.z = logf(lf + 1e-6f) * (1.0f / 6.0f);
        v.w = 0.f;
        g_ltab[t] = v;
    }
    __syncthreads();

    // --- exclusive chunk-offset scan in shared (36 threads, adds only on dep chain) ---
    if (t < FF) {
        float s = 0.f, s2 = 0.f;
        for (int ch = 0; ch < NCH; ch++) {
            int idx = ch * FF + t;
            float a = shS[idx], b = shS2[idx];
            shS[idx] = s; shS2[idx] = s2;
            s += a; s2 += b;
        }
    }
    __syncthreads();
    for (int idx = t; idx < NCH * FF; idx += blockDim.x) {
        g_partS[idx] = shS[idx]; g_partS2[idx] = shS2[idx];
    }

    // --- build piecewise-linear MLP table ---
    if (t == 0) {
        float A0 = 0.f, B0 = b2[0];
        for (int h = 0; h < HID; h++) {
            float vh = sv[h], bh = b1[h], wh = w2[h];
            if (vh > 0.f)      { stb[h] = -bh / vh; sdA[h] =  wh * vh; sdB[h] =  wh * bh; }
            else if (vh < 0.f) { stb[h] = -bh / vh; sdA[h] = -wh * vh; sdB[h] = -wh * bh;
                                 A0 += wh * vh; B0 += wh * bh; }
            else               { stb[h] = 3e38f; sdA[h] = 0.f; sdB[h] = 0.f;
                                 B0 += wh * fmaxf(bh, 0.f); }
        }
        for (int a = 1; a < HID; a++) {   // insertion sort by breakpoint
            float tb = stb[a], da = sdA[a], db = sdB[a];
            int b = a - 1;
            while (b >= 0 && stb[b] > tb) {
                stb[b + 1] = stb[b]; sdA[b + 1] = sdA[b]; sdB[b + 1] = sdB[b]; b--;
            }
            stb[b + 1] = tb; sdA[b + 1] = da; sdB[b + 1] = db;
        }
        float A = A0, B = B0;
        g_ab[0] = make_float2(A, B);
        for (int j = 0; j < HID; j++) {
            g_bp[j] = stb[j];
            A += sdA[j]; B += sdB[j];
            g_ab[j + 1] = make_float2(A, B);
        }
    }
}

// ---------------- final scan: write interleaved (S, S2) ----------------
__global__ void k_scan(const float* __restrict__ x) {
    int t = blockIdx.x * blockDim.x + threadIdx.x;
    if (t >= NCH * FF) return;
    int f = t % FF, ch = t / FF;
    float s = g_partS[t], s2 = g_partS2[t];
    if (ch == 0) ((float2*)g_P)[f] = make_float2(0.f, 0.f);   // row 0
    const float* p = x + (size_t)ch * CHROWS * FF + f;
    float2* o = (float2*)(g_P + ((size_t)ch * CHROWS + 1) * 2 * FF) + f;
    #pragma unroll 4
    for (int r = 0; r < CHROWS; r++) {
        float v = p[r * FF];
        s += v; s2 = fmaf(v, v, s2);
        o[r * FF] = make_float2(s, s2);
    }
}

// ---------------- main: one thread per (i, l) cell, f32x2-packed ----------------
__global__ __launch_bounds__(256) void k_main(float* __restrict__ out) {
    __shared__ float4 s_lt[MM];
    __shared__ float  s_bp[HID];
    __shared__ float2 s_ab[HID + 1];
    __shared__ float  s_kc;
    int t = threadIdx.x;
    if (t < MM)       s_lt[t] = g_ltab[t];
    if (t < HID)      s_bp[t] = g_bp[t];
    if (t < HID + 1)  s_ab[t] = g_ab[t];
    if (t == 0)       s_kc = g_kc;
    __syncthreads();

    int g = blockIdx.x * 256 + t;
    if (g >= LL * MM) return;
    int i   = g / MM;
    int lm1 = g - i * MM;
    int l   = lm1 + 1;
    if (i + l > LL) { out[g] = NEG_INF_V; return; }

    float4 lt  = s_lt[lm1];
    float invl = lt.x, lenf = lt.y, llf = lt.z;

    const float4* pe = (const float4*)(g_P + (size_t)(i + l) * 2 * FF);
    const float4* pi = (const float4*)(g_P + (size_t)i * 2 * FF);

    const u64 NEG1 = 0xBF800000BF800000ULL;   // (-1.0f, -1.0f)
    u64 invl2 = pk(invl, invl);
    u64 agg[FF];                               // (mean_f, var_f) packed

    #pragma unroll
    for (int j = 0; j < 18; j++) {             // 2 features per float4 pair
        float4 e4 = pe[j], i4 = pi[j];
        u64 elo = pk(e4.x, e4.y), ehi = pk(e4.z, e4.w);
        u64 ilo = pk(i4.x, i4.y), ihi = pk(i4.z, i4.w);
        u64 dlo = fma2(ilo, NEG1, elo);        // (Se-Si, Qe-Qi)
        u64 dhi = fma2(ihi, NEG1, ehi);
        u64 tlo = mul2(dlo, invl2);            // (m, q)
        u64 thi = mul2(dhi, invl2);
        float m0, q0, m1, q1;
        upk(tlo, m0, q0); upk(thi, m1, q1);
        float v0 = fmaf(-m0, m0, q0);
        float v1 = fmaf(-m1, m1, q1);
        agg[2 * j]     = pk(m0, v0);
        agg[2 * j + 1] = pk(m1, v1);
    }

    float kc = s_kc;
    float r;
    if (kc >= 0.f) {                           // uniform branch: track only the needed extremum
        r = fmaxf(lenf, llf);
        #pragma unroll
        for (int f = 0; f < FF; f++) { float a, b; upk(agg[f], a, b); r = fmaxf(r, fmaxf(a, b)); }
    } else {
        r = fminf(lenf, llf);
        #pragma unroll
        for (int f = 0; f < FF; f++) { float a, b; upk(agg[f], a, b); r = fminf(r, fminf(a, b)); }
    }
    float mz = r * kc;

    u64 kc2  = pk(kc, kc);
    u64 nmz2 = pk(-mz, -mz);
    u64 den2 = 0ULL, num2 = 0ULL;
    #pragma unroll
    for (int f = 0; f < FF; f++) {
        u64 arg = fma2(agg[f], kc2, nmz2);
        float a0, a1; upk(arg, a0, a1);
        u64 ep = pk(ex2(a0), ex2(a1));
        den2 = add2(den2, ep);
        num2 = fma2(agg[f], ep, num2);
    }
    float dl, dh, nl, nh;
    upk(den2, dl, dh); upk(num2, nl, nh);
    { float e = ex2(fmaf(lenf, kc, -mz)); dl += e; nl = fmaf(lenf, e, nl); }
    { float e = ex2(fmaf(llf,  kc, -mz)); dh += e; nh = fmaf(llf,  e, nh); }

    float s = __fdividef(nl + nh, dl + dh);

    // rank of s among sorted breakpoints (branchless, 7 steps covers 0..64)
    int lo = 0;
    #pragma unroll
    for (int st = 64; st > 0; st >>= 1) {
        int nx = lo + st;
        if (nx <= HID && s >= s_bp[nx - 1]) lo = nx;
    }
    float2 ab = s_ab[lo];
    out[g] = fmaf(ab.x, s, ab.y);
}

// ---------------- launch ----------------
extern "C" void kernel_launch(void* const* d_in, const int* in_sizes, int n_in,
                              void* d_out, int out_size) {
    const float* x  = (const float*)d_in[0];
    const float* wf = (const float*)d_in[1];
    const float* q  = (const float*)d_in[2];
    const float* w1 = (const float*)d_in[3];
    const float* b1 = (const float*)d_in[4];
    const float* w2 = (const float*)d_in[5];
    const float* b2 = (const float*)d_in[6];
    float* out = (float*)d_out;

    k_part<<<(NCH * FF) / 128, 128>>>(x);
    k_prep_off<<<1, 128>>>(wf, q, w1, b1, w2, b2);
    k_scan<<<(NCH * FF) / 128, 128>>>(x);
    k_main<<<(LL * MM) / 256, 256>>>(out);
}

// round 5
// speedup vs baseline: 3.4058x; 3.0348x over previous
#include <cuda_runtime.h>
#include <math.h>

#define LL 4096
#define FF 36
#define MM 100
#define HID 64
#define NEG_INF_V (-1e9f)

#define NCH 128
#define CHROWS 32   // NCH*CHROWS == LL

#define TI 16                    // i-values per k_main block
#define ROWS_T (TI + MM)         // 116 tile rows
#define ROWW 76                  // padded row width in floats (72 data + 4 pad)

typedef unsigned long long u64;

// ---------------- device scratch ----------------
// interleaved prefix sums: g_P[row*72 + 2f] = S, g_P[row*72 + 2f + 1] = S2
__device__ __align__(128) float g_P[(LL + 1) * 2 * FF];
__device__ float  g_partS [NCH * FF];
__device__ float  g_partS2[NCH * FF];
__device__ float  g_kc;                 // c * log2(e)
__device__ float4 g_ltab[MM];           // (1/l, l/500, log(l+1e-6)/6, 0)
__device__ float  g_bp[HID];            // sorted relu breakpoints
__device__ float2 g_ab[HID + 1];        // (slope, intercept) per bin

// ---------------- f32x2 packed helpers (sm_100) ----------------
__device__ __forceinline__ float ex2(float x) {
    float y; asm("ex2.approx.ftz.f32 %0, %1;" : "=f"(y) : "f"(x)); return y;
}
__device__ __forceinline__ u64 pk(float lo, float hi) {
    u64 r; asm("mov.b64 %0, {%1,%2};" : "=l"(r) : "f"(lo), "f"(hi)); return r;
}
__device__ __forceinline__ void upk(u64 v, float& lo, float& hi) {
    asm("mov.b64 {%0,%1}, %2;" : "=f"(lo), "=f"(hi) : "l"(v));
}
__device__ __forceinline__ u64 fma2(u64 a, u64 b, u64 c) {
    u64 d; asm("fma.rn.f32x2 %0, %1, %2, %3;" : "=l"(d) : "l"(a), "l"(b), "l"(c)); return d;
}
__device__ __forceinline__ u64 add2(u64 a, u64 b) {
    u64 d; asm("add.rn.f32x2 %0, %1, %2;" : "=l"(d) : "l"(a), "l"(b)); return d;
}
__device__ __forceinline__ u64 mul2(u64 a, u64 b) {
    u64 d; asm("mul.rn.f32x2 %0, %1, %2;" : "=l"(d) : "l"(a), "l"(b)); return d;
}

// ---------------- chunk partials ----------------
__global__ void k_part(const float* __restrict__ x) {
    int t = blockIdx.x * blockDim.x + threadIdx.x;
    if (t >= NCH * FF) return;
    int f = t % FF, ch = t / FF;
    const float* p = x + (size_t)ch * CHROWS * FF + f;
    float s = 0.f, s2 = 0.f;
    #pragma unroll 8
    for (int r = 0; r < CHROWS; r++) {
        float v = p[r * FF];
        s += v; s2 = fmaf(v, v, s2);
    }
    g_partS[t] = s; g_partS2[t] = s2;
}

// ---------------- merged prep (parallel rank-sort MLP collapse) + chunk-offset scan ----------------
__global__ void k_prep_off(const float* __restrict__ wf, const float* __restrict__ q,
                           const float* __restrict__ w1, const float* __restrict__ b1,
                           const float* __restrict__ w2, const float* __restrict__ b2) {
    __shared__ float stb[HID], sdA[HID], sdB[HID];
    __shared__ float ssA[HID], ssB[HID];
    __shared__ float redA[HID], redB[HID];
    __shared__ float sA0B0[2];
    __shared__ float shS[NCH * FF], shS2[NCH * FF];
    int t = threadIdx.x;   // 128 threads

    // --- stage chunk partials into shared ---
    for (int idx = t; idx < NCH * FF; idx += blockDim.x) {
        shS[idx] = g_partS[idx]; shS2[idx] = g_partS2[idx];
    }

    // --- per-hidden-unit table entries (64 threads in parallel) ---
    if (t < HID) {
        float vh = 0.f;
        #pragma unroll
        for (int a = 0; a < 32; a++) vh = fmaf(wf[a], w1[a * HID + t], vh);
        float bh = b1[t], wh = w2[t];
        float tb, dA, dB, cA0 = 0.f, cB0 = 0.f;
        if (vh > 0.f)      { tb = -bh / vh; dA =  wh * vh; dB =  wh * bh; }
        else if (vh < 0.f) { tb = -bh / vh; dA = -wh * vh; dB = -wh * bh;
                             cA0 = wh * vh; cB0 = wh * bh; }
        else               { tb = 3e38f; dA = 0.f; dB = 0.f;
                             cB0 = wh * fmaxf(bh, 0.f); }
        stb[t] = tb; sdA[t] = dA; sdB[t] = dB;
        redA[t] = cA0; redB[t] = cB0;
    }
    if (t == 0) {
        float c = 0.f;
        #pragma unroll
        for (int a = 0; a < 32; a++) c = fmaf(wf[a], q[a], c);
        g_kc = c * 1.4426950408889634f;
    }
    if (t < MM) {
        float lf = (float)(t + 1);
        float4 v;
        v.x = 1.0f / lf;
        v.y = lf * (1.0f / 500.0f);
        v.z = logf(lf + 1e-6f) * (1.0f / 6.0f);
        v.w = 0.f;
        g_ltab[t] = v;
    }
    __syncthreads();

    // --- A0/B0 reduction ---
    if (t == 0) {
        float A0 = 0.f, B0 = b2[0];
        #pragma unroll
        for (int h = 0; h < HID; h++) { A0 += redA[h]; B0 += redB[h]; }
        sA0B0[0] = A0; sA0B0[1] = B0;
    }

    // --- stable rank sort + scatter ---
    if (t < HID) {
        float tb = stb[t];
        int rank = 0;
        #pragma unroll
        for (int k = 0; k < HID; k++) {
            float o = stb[k];
            rank += (o < tb) || (o == tb && k < t);
        }
        ssA[rank] = sdA[t]; ssB[rank] = sdB[t];
        g_bp[rank] = tb;
    }

    // --- exclusive chunk-offset scan in shared ---
    if (t >= 64 && t - 64 < FF) {
        int f = t - 64;
        float s = 0.f, s2 = 0.f;
        for (int ch = 0; ch < NCH; ch++) {
            int idx = ch * FF + f;
            float a = shS[idx], b = shS2[idx];
            shS[idx] = s; shS2[idx] = s2;
            s += a; s2 += b;
        }
    }
    __syncthreads();

    // --- prefix (A, B) per bin ---
    if (t <= HID) {
        float A = sA0B0[0], B = sA0B0[1];
        for (int k = 0; k < t; k++) { A += ssA[k]; B += ssB[k]; }
        g_ab[t] = make_float2(A, B);
    }
    for (int idx = t; idx < NCH * FF; idx += blockDim.x) {
        g_partS[idx] = shS[idx]; g_partS2[idx] = shS2[idx];
    }
}

// ---------------- final scan: write interleaved (S, S2) ----------------
__global__ void k_scan(const float* __restrict__ x) {
    int t = blockIdx.x * blockDim.x + threadIdx.x;
    if (t >= NCH * FF) return;
    int f = t % FF, ch = t / FF;
    float s = g_partS[t], s2 = g_partS2[t];
    if (ch == 0) ((float2*)g_P)[f] = make_float2(0.f, 0.f);   // row 0
    const float* p = x + (size_t)ch * CHROWS * FF + f;
    float2* o = (float2*)(g_P + ((size_t)ch * CHROWS + 1) * 2 * FF) + f;
    #pragma unroll 4
    for (int r = 0; r < CHROWS; r++) {
        float v = p[r * FF];
        s += v; s2 = fmaf(v, v, s2);
        o[r * FF] = make_float2(s, s2);
    }
}

// ---------------- main: tile of TI i-values x all l, rows staged in shared ----------------
__global__ __launch_bounds__(256) void k_main(float* __restrict__ out) {
    __shared__ float  sh[ROWS_T * ROWW];     // padded rows: conflict-free LDS.128 at stride 1 row
    __shared__ float4 s_lt[MM];
    __shared__ float  s_bp[HID];
    __shared__ float2 s_ab[HID + 1];
    __shared__ float  s_kc;
    int t = threadIdx.x;
    int i0 = blockIdx.x * TI;

    if (t < MM)       s_lt[t] = g_ltab[t];
    if (t < HID)      s_bp[t] = g_bp[t];
    if (t < HID + 1)  s_ab[t] = g_ab[t];
    if (t == 0)       s_kc = g_kc;

    // stage tile rows [i0, i0+ROWS_T) of g_P (72 floats each) into padded shared rows
    {
        int nrows = min(ROWS_T, LL + 1 - i0);
        int total = nrows * 18;                    // float4 per row
        const float4* src = (const float4*)(g_P + (size_t)i0 * 2 * FF);
        for (int idx = t; idx < total; idx += 256) {
            int r = idx / 18, c = idx % 18;
            *(float4*)&sh[r * ROWW + c * 4] = src[r * 18 + c];
        }
    }
    __syncthreads();

    float kc = s_kc;
    u64 kc2 = pk(kc, kc);
    const u64 NEG1 = 0xBF800000BF800000ULL;

    #pragma unroll 1
    for (int c = t; c < TI * MM; c += 256) {
        int li  = c / MM;
        int lm1 = c - li * MM;
        int l   = lm1 + 1;
        int gout = i0 * MM + c;
        if (i0 + li + l > LL) { out[gout] = NEG_INF_V; continue; }

        float4 lt  = s_lt[lm1];
        float invl = lt.x, lenf = lt.y, llf = lt.z;

        const float4* pe = (const float4*)&sh[(li + l) * ROWW];
        const float4* pi = (const float4*)&sh[li * ROWW];

        u64 invl2 = pk(invl, invl);
        u64 agg[FF];                               // (mean_f, var_f) packed

        #pragma unroll
        for (int j = 0; j < 18; j++) {             // 2 features per float4 pair
            float4 e4 = pe[j], i4 = pi[j];
            u64 elo = pk(e4.x, e4.y), ehi = pk(e4.z, e4.w);
            u64 ilo = pk(i4.x, i4.y), ihi = pk(i4.z, i4.w);
            u64 dlo = fma2(ilo, NEG1, elo);        // (Se-Si, Qe-Qi)
            u64 dhi = fma2(ihi, NEG1, ehi);
            u64 tlo = mul2(dlo, invl2);            // (m, q)
            u64 thi = mul2(dhi, invl2);
            float m0, q0, m1, q1;
            upk(tlo, m0, q0); upk(thi, m1, q1);
            float v0 = fmaf(-m0, m0, q0);
            float v1 = fmaf(-m1, m1, q1);
            agg[2 * j]     = pk(m0, v0);
            agg[2 * j + 1] = pk(m1, v1);
        }

        float r;
        if (kc >= 0.f) {
            r = fmaxf(lenf, llf);
            #pragma unroll
            for (int f = 0; f < FF; f++) { float a, b; upk(agg[f], a, b); r = fmaxf(r, fmaxf(a, b)); }
        } else {
            r = fminf(lenf, llf);
            #pragma unroll
            for (int f = 0; f < FF; f++) { float a, b; upk(agg[f], a, b); r = fminf(r, fminf(a, b)); }
        }
        float mz = r * kc;

        u64 nmz2 = pk(-mz, -mz);
        u64 den2 = 0ULL, num2 = 0ULL;
        #pragma unroll
        for (int f = 0; f < FF; f++) {
            u64 arg = fma2(agg[f], kc2, nmz2);
            float a0, a1; upk(arg, a0, a1);
            u64 ep = pk(ex2(a0), ex2(a1));
            den2 = add2(den2, ep);
            num2 = fma2(agg[f], ep, num2);
        }
        float dl, dh, nl, nh;
        upk(den2, dl, dh); upk(num2, nl, nh);
        { float e = ex2(fmaf(lenf, kc, -mz)); dl += e; nl = fmaf(lenf, e, nl); }
        { float e = ex2(fmaf(llf,  kc, -mz)); dh += e; nh = fmaf(llf,  e, nh); }

        float s = __fdividef(nl + nh, dl + dh);

        // rank of s among sorted breakpoints (branchless, 7 steps covers 0..64)
        int lo = 0;
        #pragma unroll
        for (int st = 64; st > 0; st >>= 1) {
            int nx = lo + st;
            if (nx <= HID && s >= s_bp[nx - 1]) lo = nx;
        }
        float2 ab = s_ab[lo];
        out[gout] = fmaf(ab.x, s, ab.y);
    }
}

// ---------------- launch ----------------
extern "C" void kernel_launch(void* const* d_in, const int* in_sizes, int n_in,
                              void* d_out, int out_size) {
    const float* x  = (const float*)d_in[0];
    const float* wf = (const float*)d_in[1];
    const float* q  = (const float*)d_in[2];
    const float* w1 = (const float*)d_in[3];
    const float* b1 = (const float*)d_in[4];
    const float* w2 = (const float*)d_in[5];
    const float* b2 = (const float*)d_in[6];
    float* out = (float*)d_out;

    k_part<<<(NCH * FF) / 128, 128>>>(x);
    k_prep_off<<<1, 128>>>(wf, q, w1, b1, w2, b2);
    k_scan<<<(NCH * FF) / 128, 128>>>(x);
    k_main<<<LL / TI, 256>>>(out);
}

// round 6
// speedup vs baseline: 3.4390x; 1.0098x over previous
#include <cuda_runtime.h>
#include <math.h>

#define LL 4096
#define FF 36
#define MM 100
#define HID 64
#define NEG_INF_V (-1e9f)

#define NCH 128
#define CHROWS 32   // NCH*CHROWS == LL

#define TI 16                    // i-values per k_main block
#define ROWS_T (TI + MM)         // 116 tile rows
#define ROWW 76                  // padded row width in floats (72 data + 4 pad)

typedef unsigned long long u64;

// ---------------- device scratch ----------------
__device__ __align__(128) float g_P[(LL + 1) * 2 * FF];   // interleaved (S, S2)
__device__ float  g_partS [NCH * FF];
__device__ float  g_partS2[NCH * FF];
__device__ float  g_kc;                 // c * log2(e)
__device__ float4 g_ltab[MM];           // (1/l, l/500, log(l+1e-6)/6, 0)
__device__ float  g_bp[HID];            // sorted relu breakpoints
__device__ float2 g_ab[HID + 1];        // (slope, intercept) per bin

// ---------------- f32x2 packed helpers (sm_100) ----------------
__device__ __forceinline__ float ex2(float x) {
    float y; asm("ex2.approx.ftz.f32 %0, %1;" : "=f"(y) : "f"(x)); return y;
}
__device__ __forceinline__ u64 pk(float lo, float hi) {
    u64 r; asm("mov.b64 %0, {%1,%2};" : "=l"(r) : "f"(lo), "f"(hi)); return r;
}
__device__ __forceinline__ void upk(u64 v, float& lo, float& hi) {
    asm("mov.b64 {%0,%1}, %2;" : "=f"(lo), "=f"(hi) : "l"(v));
}
__device__ __forceinline__ u64 fma2(u64 a, u64 b, u64 c) {
    u64 d; asm("fma.rn.f32x2 %0, %1, %2, %3;" : "=l"(d) : "l"(a), "l"(b), "l"(c)); return d;
}
__device__ __forceinline__ u64 add2(u64 a, u64 b) {
    u64 d; asm("add.rn.f32x2 %0, %1, %2;" : "=l"(d) : "l"(a), "l"(b)); return d;
}
__device__ __forceinline__ u64 mul2(u64 a, u64 b) {
    u64 d; asm("mul.rn.f32x2 %0, %1, %2;" : "=l"(d) : "l"(a), "l"(b)); return d;
}

// ---------------- chunk partials ----------------
__global__ void k_part(const float* __restrict__ x) {
    int t = blockIdx.x * blockDim.x + threadIdx.x;
    if (t >= NCH * FF) return;
    int f = t % FF, ch = t / FF;
    const float* p = x + (size_t)ch * CHROWS * FF + f;
    float s = 0.f, s2 = 0.f;
    #pragma unroll 8
    for (int r = 0; r < CHROWS; r++) {
        float v = p[r * FF];
        s += v; s2 = fmaf(v, v, s2);
    }
    g_partS[t] = s; g_partS2[t] = s2;
}

// ---------------- merged prep (parallel rank-sort MLP collapse) + chunk-offset scan ----------------
__global__ void k_prep_off(const float* __restrict__ wf, const float* __restrict__ q,
                           const float* __restrict__ w1, const float* __restrict__ b1,
                           const float* __restrict__ w2, const float* __restrict__ b2) {
    __shared__ float stb[HID], sdA[HID], sdB[HID];
    __shared__ float ssA[HID], ssB[HID];
    __shared__ float redA[HID], redB[HID];
    __shared__ float sA0B0[2];
    __shared__ float shS[NCH * FF], shS2[NCH * FF];
    int t = threadIdx.x;   // 128 threads

    for (int idx = t; idx < NCH * FF; idx += blockDim.x) {
        shS[idx] = g_partS[idx]; shS2[idx] = g_partS2[idx];
    }

    if (t < HID) {
        float vh = 0.f;
        #pragma unroll
        for (int a = 0; a < 32; a++) vh = fmaf(wf[a], w1[a * HID + t], vh);
        float bh = b1[t], wh = w2[t];
        float tb, dA, dB, cA0 = 0.f, cB0 = 0.f;
        if (vh > 0.f)      { tb = -bh / vh; dA =  wh * vh; dB =  wh * bh; }
        else if (vh < 0.f) { tb = -bh / vh; dA = -wh * vh; dB = -wh * bh;
                             cA0 = wh * vh; cB0 = wh * bh; }
        else               { tb = 3e38f; dA = 0.f; dB = 0.f;
                             cB0 = wh * fmaxf(bh, 0.f); }
        stb[t] = tb; sdA[t] = dA; sdB[t] = dB;
        redA[t] = cA0; redB[t] = cB0;
    }
    if (t == 0) {
        float c = 0.f;
        #pragma unroll
        for (int a = 0; a < 32; a++) c = fmaf(wf[a], q[a], c);
        g_kc = c * 1.4426950408889634f;
    }
    if (t < MM) {
        float lf = (float)(t + 1);
        float4 v;
        v.x = 1.0f / lf;
        v.y = lf * (1.0f / 500.0f);
        v.z = logf(lf + 1e-6f) * (1.0f / 6.0f);
        v.w = 0.f;
        g_ltab[t] = v;
    }
    __syncthreads();

    if (t == 0) {
        float A0 = 0.f, B0 = b2[0];
        #pragma unroll
        for (int h = 0; h < HID; h++) { A0 += redA[h]; B0 += redB[h]; }
        sA0B0[0] = A0; sA0B0[1] = B0;
    }

    if (t < HID) {   // stable rank sort + scatter
        float tb = stb[t];
        int rank = 0;
        #pragma unroll
        for (int k = 0; k < HID; k++) {
            float o = stb[k];
            rank += (o < tb) || (o == tb && k < t);
        }
        ssA[rank] = sdA[t]; ssB[rank] = sdB[t];
        g_bp[rank] = tb;
    }

    if (t >= 64 && t - 64 < FF) {   // exclusive chunk-offset scan
        int f = t - 64;
        float s = 0.f, s2 = 0.f;
        for (int ch = 0; ch < NCH; ch++) {
            int idx = ch * FF + f;
            float a = shS[idx], b = shS2[idx];
            shS[idx] = s; shS2[idx] = s2;
            s += a; s2 += b;
        }
    }
    __syncthreads();

    if (t <= HID) {
        float A = sA0B0[0], B = sA0B0[1];
        for (int k = 0; k < t; k++) { A += ssA[k]; B += ssB[k]; }
        g_ab[t] = make_float2(A, B);
    }
    for (int idx = t; idx < NCH * FF; idx += blockDim.x) {
        g_partS[idx] = shS[idx]; g_partS2[idx] = shS2[idx];
    }
}

// ---------------- final scan: write interleaved (S, S2) ----------------
__global__ void k_scan(const float* __restrict__ x) {
    int t = blockIdx.x * blockDim.x + threadIdx.x;
    if (t >= NCH * FF) return;
    int f = t % FF, ch = t / FF;
    float s = g_partS[t], s2 = g_partS2[t];
    if (ch == 0) ((float2*)g_P)[f] = make_float2(0.f, 0.f);
    const float* p = x + (size_t)ch * CHROWS * FF + f;
    float2* o = (float2*)(g_P + ((size_t)ch * CHROWS + 1) * 2 * FF) + f;
    #pragma unroll 4
    for (int r = 0; r < CHROWS; r++) {
        float v = p[r * FF];
        s += v; s2 = fmaf(v, v, s2);
        o[r * FF] = make_float2(s, s2);
    }
}

// ---------------- main: online softmax, no agg[] array -> low regs, high occ ----------------
__global__ __launch_bounds__(256, 4) void k_main(float* __restrict__ out) {
    __shared__ float  sh[ROWS_T * ROWW];
    __shared__ float4 s_lt[MM];
    __shared__ float  s_bp[HID];
    __shared__ float2 s_ab[HID + 1];
    __shared__ float  s_kc;
    int t = threadIdx.x;
    int i0 = blockIdx.x * TI;

    if (t < MM)       s_lt[t] = g_ltab[t];
    if (t < HID)      s_bp[t] = g_bp[t];
    if (t < HID + 1)  s_ab[t] = g_ab[t];
    if (t == 0)       s_kc = g_kc;

    {   // stage tile rows [i0, i0+ROWS_T) of g_P into padded shared rows
        int nrows = min(ROWS_T, LL + 1 - i0);
        int total = nrows * 18;
        const float4* src = (const float4*)(g_P + (size_t)i0 * 2 * FF);
        for (int idx = t; idx < total; idx += 256) {
            int r = idx / 18, c = idx % 18;
            *(float4*)&sh[r * ROWW + c * 4] = src[r * 18 + c];
        }
    }
    __syncthreads();

    float kc = s_kc;
    u64 kc2 = pk(kc, kc);
    const u64 NEG1 = 0xBF800000BF800000ULL;

    #pragma unroll 1
    for (int c = t; c < TI * MM; c += 256) {
        int li  = c / MM;
        int lm1 = c - li * MM;
        int l   = lm1 + 1;
        int gout = i0 * MM + c;
        if (i0 + li + l > LL) { out[gout] = NEG_INF_V; continue; }

        float4 lt  = s_lt[lm1];
        float invl = lt.x, lenf = lt.y, llf = lt.z;

        const float4* pe = (const float4*)&sh[(li + l) * ROWW];
        const float4* pi = (const float4*)&sh[li * ROWW];

        u64 invl2 = pk(invl, invl);

        // online softmax init from the two length features
        float aL = lenf * kc, aG = llf * kc;
        float m = fmaxf(aL, aG);
        u64 den2 = pk(ex2(aL - m), ex2(aG - m));
        u64 num2 = pk(lenf, llf);
        num2 = mul2(num2, den2);

        #pragma unroll
        for (int j = 0; j < 18; j++) {         // 4 features per iteration
            float4 e4 = pe[j], i4 = pi[j];
            u64 elo = pk(e4.x, e4.y), ehi = pk(e4.z, e4.w);
            u64 ilo = pk(i4.x, i4.y), ihi = pk(i4.z, i4.w);
            u64 dlo = fma2(ilo, NEG1, elo);    // (Se-Si, Qe-Qi)
            u64 dhi = fma2(ihi, NEG1, ehi);
            u64 tlo = mul2(dlo, invl2);        // (m, q)
            u64 thi = mul2(dhi, invl2);
            float m0, q0, m1, q1;
            upk(tlo, m0, q0); upk(thi, m1, q1);
            float v0 = fmaf(-m0, m0, q0);
            float v1 = fmaf(-m1, m1, q1);
            u64 ag0 = pk(m0, v0);
            u64 ag1 = pk(m1, v1);
            u64 ar0 = mul2(ag0, kc2);          // args
            u64 ar1 = mul2(ag1, kc2);
            float a0, a1, a2, a3;
            upk(ar0, a0, a1); upk(ar1, a2, a3);
            float mn = fmaxf(fmaxf(m, fmaxf(a0, a1)), fmaxf(a2, a3));
            float sc = ex2(m - mn);
            m = mn;
            u64 ep0 = pk(ex2(a0 - mn), ex2(a1 - mn));
            u64 ep1 = pk(ex2(a2 - mn), ex2(a3 - mn));
            u64 sc2 = pk(sc, sc);
            den2 = fma2(den2, sc2, add2(ep0, ep1));
            num2 = fma2(num2, sc2, fma2(ag0, ep0, mul2(ag1, ep1)));
        }

        float dl, dh, nl, nh;
        upk(den2, dl, dh); upk(num2, nl, nh);
        float s = __fdividef(nl + nh, dl + dh);

        // rank of s among sorted breakpoints (branchless)
        int lo = 0;
        #pragma unroll
        for (int st = 64; st > 0; st >>= 1) {
            int nx = lo + st;
            if (nx <= HID && s >= s_bp[nx - 1]) lo = nx;
        }
        float2 ab = s_ab[lo];
        out[gout] = fmaf(ab.x, s, ab.y);
    }
}

// ---------------- launch ----------------
extern "C" void kernel_launch(void* const* d_in, const int* in_sizes, int n_in,
                              void* d_out, int out_size) {
    const float* x  = (const float*)d_in[0];
    const float* wf = (const float*)d_in[1];
    const float* q  = (const float*)d_in[2];
    const float* w1 = (const float*)d_in[3];
    const float* b1 = (const float*)d_in[4];
    const float* w2 = (const float*)d_in[5];
    const float* b2 = (const float*)d_in[6];
    float* out = (float*)d_out;

    k_part<<<(NCH * FF) / 128, 128>>>(x);
    k_prep_off<<<1, 128>>>(wf, q, w1, b1, w2, b2);
    k_scan<<<(NCH * FF) / 128, 128>>>(x);
    k_main<<<LL / TI, 256>>>(out);
}

// round 8
// speedup vs baseline: 3.6642x; 1.0655x over previous
#include <cuda_runtime.h>
#include <math.h>

#define LL 4096
#define FF 36
#define MM 100
#define HID 64
#define NEG_INF_V (-1e9f)

#define NCH 128
#define CHROWS 32   // NCH*CHROWS == LL

#define TI 8                     // i-values per k_main block
#define ROWS_T (TI + MM)         // 108 tile rows
#define ROWW 76                  // padded row width in floats (72 data + 4 pad)

typedef unsigned long long u64;

// ---------------- device scratch ----------------
__device__ __align__(128) float g_P[(LL + 1) * 2 * FF];   // interleaved (S, S2)
__device__ float  g_partS [NCH * FF];
__device__ float  g_partS2[NCH * FF];
__device__ float  g_kc;                 // c * log2(e)
__device__ float4 g_ltab[MM];           // (1/l, l/500, log(l+1e-6)/6, 0)
__device__ float  g_bp[HID];            // sorted relu breakpoints
__device__ float2 g_ab[HID + 1];        // (slope, intercept) per bin

// ---------------- f32x2 packed helpers (sm_100) ----------------
__device__ __forceinline__ float ex2(float x) {
    float y; asm("ex2.approx.ftz.f32 %0, %1;" : "=f"(y) : "f"(x)); return y;
}
__device__ __forceinline__ u64 pk(float lo, float hi) {
    u64 r; asm("mov.b64 %0, {%1,%2};" : "=l"(r) : "f"(lo), "f"(hi)); return r;
}
__device__ __forceinline__ void upk(u64 v, float& lo, float& hi) {
    asm("mov.b64 {%0,%1}, %2;" : "=f"(lo), "=f"(hi) : "l"(v));
}
__device__ __forceinline__ u64 fma2(u64 a, u64 b, u64 c) {
    u64 d; asm("fma.rn.f32x2 %0, %1, %2, %3;" : "=l"(d) : "l"(a), "l"(b), "l"(c)); return d;
}
__device__ __forceinline__ u64 add2(u64 a, u64 b) {
    u64 d; asm("add.rn.f32x2 %0, %1, %2;" : "=l"(d) : "l"(a), "l"(b)); return d;
}
__device__ __forceinline__ u64 mul2(u64 a, u64 b) {
    u64 d; asm("mul.rn.f32x2 %0, %1, %2;" : "=l"(d) : "l"(a), "l"(b)); return d;
}

// ---------------- k1: chunk partials; block 0 also builds MLP/l tables ----------------
__global__ void k_part(const float* __restrict__ x,
                       const float* __restrict__ wf, const float* __restrict__ q,
                       const float* __restrict__ w1, const float* __restrict__ b1,
                       const float* __restrict__ w2, const float* __restrict__ b2) {
    int t = threadIdx.x;
    int g = blockIdx.x * 128 + t;

    if (blockIdx.x == 0) {   // weight-only prep, runs alongside partials
        __shared__ float stb[HID], sdA[HID], sdB[HID];
        __shared__ float ssA[HID], ssB[HID];
        __shared__ float redA[HID], redB[HID];
        __shared__ float sA0B0[2];

        if (t < HID) {
            float vh = 0.f;
            #pragma unroll
            for (int a = 0; a < 32; a++) vh = fmaf(wf[a], w1[a * HID + t], vh);
            float bh = b1[t], wh = w2[t];
            float tb, dA, dB, cA0 = 0.f, cB0 = 0.f;
            if (vh > 0.f)      { tb = -bh / vh; dA =  wh * vh; dB =  wh * bh; }
            else if (vh < 0.f) { tb = -bh / vh; dA = -wh * vh; dB = -wh * bh;
                                 cA0 = wh * vh; cB0 = wh * bh; }
            else               { tb = 3e38f; dA = 0.f; dB = 0.f;
                                 cB0 = wh * fmaxf(bh, 0.f); }
            stb[t] = tb; sdA[t] = dA; sdB[t] = dB;
            redA[t] = cA0; redB[t] = cB0;
        }
        if (t == 0) {
            float c = 0.f;
            #pragma unroll
            for (int a = 0; a < 32; a++) c = fmaf(wf[a], q[a], c);
            g_kc = c * 1.4426950408889634f;
        }
        if (t < MM) {
            float lf = (float)(t + 1);
            float4 v;
            v.x = 1.0f / lf;
            v.y = lf * (1.0f / 500.0f);
            v.z = logf(lf + 1e-6f) * (1.0f / 6.0f);
            v.w = 0.f;
            g_ltab[t] = v;
        }
        __syncthreads();
        if (t == 0) {
            float A0 = 0.f, B0 = b2[0];
            #pragma unroll
            for (int h = 0; h < HID; h++) { A0 += redA[h]; B0 += redB[h]; }
            sA0B0[0] = A0; sA0B0[1] = B0;
        }
        if (t < HID) {   // stable rank sort + scatter
            float tb = stb[t];
            int rank = 0;
            #pragma unroll
            for (int k = 0; k < HID; k++) {
                float o = stb[k];
                rank += (o < tb) || (o == tb && k < t);
            }
            ssA[rank] = sdA[t]; ssB[rank] = sdB[t];
            g_bp[rank] = tb;
        }
        __syncthreads();
        if (t <= HID) {
            float A = sA0B0[0], B = sA0B0[1];
            for (int k = 0; k < t; k++) { A += ssA[k]; B += ssB[k]; }
            g_ab[t] = make_float2(A, B);
        }
    }

    if (g < NCH * FF) {
        int f = g % FF, ch = g / FF;
        const float* p = x + (size_t)ch * CHROWS * FF + f;
        float s = 0.f, s2 = 0.f;
        #pragma unroll 8
        for (int r = 0; r < CHROWS; r++) {
            float v = p[r * FF];
            s += v; s2 = fmaf(v, v, s2);
        }
        g_partS[g] = s; g_partS2[g] = s2;
    }
}

// ---------------- k2: per-block offset recompute + final scan, interleaved output ----------------
__global__ void k_scan(const float* __restrict__ x) {
    __shared__ float shS[NCH * FF], shS2[NCH * FF];   // 36 KB
    int t = threadIdx.x;
    int g = blockIdx.x * 128 + t;

    for (int idx = t; idx < NCH * FF; idx += 128) {
        shS[idx] = g_partS[idx]; shS2[idx] = g_partS2[idx];
    }
    __syncthreads();

    if (g >= NCH * FF) return;
    int f = g % FF, ch = g / FF;

    // exclusive prefix over chunks for this feature
    float s = 0.f, s2 = 0.f;
    for (int c = 0; c < ch; c++) {
        s += shS[c * FF + f]; s2 += shS2[c * FF + f];
    }

    if (ch == 0) ((float2*)g_P)[f] = make_float2(0.f, 0.f);   // row 0
    const float* p = x + (size_t)ch * CHROWS * FF + f;
    float2* o = (float2*)(g_P + ((size_t)ch * CHROWS + 1) * 2 * FF) + f;
    #pragma unroll 4
    for (int r = 0; r < CHROWS; r++) {
        float v = p[r * FF];
        s += v; s2 = fmaf(v, v, s2);
        o[r * FF] = make_float2(s, s2);
    }
}

// ---------------- k3: main, online softmax, TI=8 -> grid 512 (one full wave @ 4 CTA/SM) ----------------
__global__ __launch_bounds__(256, 4) void k_main(float* __restrict__ out) {
    __shared__ float  sh[ROWS_T * ROWW];
    __shared__ float4 s_lt[MM];
    __shared__ float  s_bp[HID];
    __shared__ float2 s_ab[HID + 1];
    __shared__ float  s_kc;
    int t = threadIdx.x;
    int i0 = blockIdx.x * TI;

    if (t < MM)       s_lt[t] = g_ltab[t];
    if (t < HID)      s_bp[t] = g_bp[t];
    if (t < HID + 1)  s_ab[t] = g_ab[t];
    if (t == 0)       s_kc = g_kc;

    {   // stage tile rows [i0, i0+ROWS_T) of g_P into padded shared rows
        int nrows = min(ROWS_T, LL + 1 - i0);
        int total = nrows * 18;
        const float4* src = (const float4*)(g_P + (size_t)i0 * 2 * FF);
        for (int idx = t; idx < total; idx += 256) {
            int r = idx / 18, c = idx % 18;
            *(float4*)&sh[r * ROWW + c * 4] = src[r * 18 + c];
        }
    }
    __syncthreads();

    float kc = s_kc;
    u64 kc2 = pk(kc, kc);
    const u64 NEG1 = 0xBF800000BF800000ULL;

    #pragma unroll 1
    for (int c = t; c < TI * MM; c += 256) {
        int li  = c / MM;
        int lm1 = c - li * MM;
        int l   = lm1 + 1;
        int gout = i0 * MM + c;
        if (i0 + li + l > LL) { out[gout] = NEG_INF_V; continue; }

        float4 lt  = s_lt[lm1];
        float invl = lt.x, lenf = lt.y, llf = lt.z;

        const float4* pe = (const float4*)&sh[(li + l) * ROWW];
        const float4* pi = (const float4*)&sh[li * ROWW];

        u64 invl2 = pk(invl, invl);

        // online softmax init from the two length features
        float aL = lenf * kc, aG = llf * kc;
        float m = fmaxf(aL, aG);
        u64 den2 = pk(ex2(aL - m), ex2(aG - m));
        u64 num2 = pk(lenf, llf);
        num2 = mul2(num2, den2);

        #pragma unroll
        for (int j = 0; j < 18; j++) {         // 4 features per iteration
            float4 e4 = pe[j], i4 = pi[j];
            u64 elo = pk(e4.x, e4.y), ehi = pk(e4.z, e4.w);
            u64 ilo = pk(i4.x, i4.y), ihi = pk(i4.z, i4.w);
            u64 dlo = fma2(ilo, NEG1, elo);    // (Se-Si, Qe-Qi)
            u64 dhi = fma2(ihi, NEG1, ehi);
            u64 tlo = mul2(dlo, invl2);        // (m, q)
            u64 thi = mul2(dhi, invl2);
            float m0, q0, m1, q1;
            upk(tlo, m0, q0); upk(thi, m1, q1);
            float v0 = fmaf(-m0, m0, q0);
            float v1 = fmaf(-m1, m1, q1);
            u64 ag0 = pk(m0, v0);
            u64 ag1 = pk(m1, v1);
            u64 ar0 = mul2(ag0, kc2);          // args
            u64 ar1 = mul2(ag1, kc2);
            float a0, a1, a2, a3;
            upk(ar0, a0, a1); upk(ar1, a2, a3);
            float mn = fmaxf(fmaxf(m, fmaxf(a0, a1)), fmaxf(a2, a3));
            float sc = ex2(m - mn);
            m = mn;
            u64 ep0 = pk(ex2(a0 - mn), ex2(a1 - mn));
            u64 ep1 = pk(ex2(a2 - mn), ex2(a3 - mn));
            u64 sc2 = pk(sc, sc);
            den2 = fma2(den2, sc2, add2(ep0, ep1));
            num2 = fma2(num2, sc2, fma2(ag0, ep0, mul2(ag1, ep1)));
        }

        float dl, dh, nl, nh;
        upk(den2, dl, dh); upk(num2, nl, nh);
        float s = __fdividef(nl + nh, dl + dh);

        // rank of s among sorted breakpoints (branchless)
        int lo = 0;
        #pragma unroll
        for (int st = 64; st > 0; st >>= 1) {
            int nx = lo + st;
            if (nx <= HID && s >= s_bp[nx - 1]) lo = nx;
        }
        float2 ab = s_ab[lo];
        out[gout] = fmaf(ab.x, s, ab.y);
    }
}

// ---------------- launch ----------------
extern "C" void kernel_launch(void* const* d_in, const int* in_sizes, int n_in,
                              void* d_out, int out_size) {
    const float* x  = (const float*)d_in[0];
    const float* wf = (const float*)d_in[1];
    const float* q  = (const float*)d_in[2];
    const float* w1 = (const float*)d_in[3];
    const float* b1 = (const float*)d_in[4];
    const float* w2 = (const float*)d_in[5];
    const float* b2 = (const float*)d_in[6];
    float* out = (float*)d_out;

    k_part<<<(NCH * FF + 127) / 128, 128>>>(x, wf, q, w1, b1, w2, b2);
    k_scan<<<(NCH * FF + 127) / 128, 128>>>(x);
    k_main<<<LL / TI, 256>>>(out);
}

// round 10
// speedup vs baseline: 4.1325x; 1.1278x over previous
#include <cuda_runtime.h>
#include <math.h>

#define LL 4096
#define FF 36
#define MM 100
#define HID 64
#define NEG_INF_V (-1e9f)

#define NCH 512
#define CHROWS 8     // NCH*CHROWS == LL

#define TI 8                     // i-values per k_main block
#define ROWS_T (TI + MM)         // 108 tile rows
#define ROWW 76                  // padded row width in floats (72 data + 4 pad)

typedef unsigned long long u64;

// ---------------- device scratch ----------------
__device__ __align__(128) float g_P[(LL + 1) * 2 * FF];     // interleaved (S, S2)
__device__ __align__(128) float2 g_part2[FF * NCH];          // feature-major chunk partials
__device__ float  g_kc;                 // c * log2(e)
__device__ float4 g_ltab[MM];           // (1/l, l/500, log(l+1e-6)/6, 0)
__device__ float  g_bp[HID];            // sorted relu breakpoints
__device__ float2 g_ab[HID + 1];        // (slope, intercept) per bin

// ---------------- f32x2 packed helpers (sm_100) ----------------
__device__ __forceinline__ float ex2(float x) {
    float y; asm("ex2.approx.ftz.f32 %0, %1;" : "=f"(y) : "f"(x)); return y;
}
__device__ __forceinline__ u64 pk(float lo, float hi) {
    u64 r; asm("mov.b64 %0, {%1,%2};" : "=l"(r) : "f"(lo), "f"(hi)); return r;
}
__device__ __forceinline__ void upk(u64 v, float& lo, float& hi) {
    asm("mov.b64 {%0,%1}, %2;" : "=f"(lo), "=f"(hi) : "l"(v));
}
__device__ __forceinline__ u64 fma2(u64 a, u64 b, u64 c) {
    u64 d; asm("fma.rn.f32x2 %0, %1, %2, %3;" : "=l"(d) : "l"(a), "l"(b), "l"(c)); return d;
}
__device__ __forceinline__ u64 add2(u64 a, u64 b) {
    u64 d; asm("add.rn.f32x2 %0, %1, %2;" : "=l"(d) : "l"(a), "l"(b)); return d;
}
__device__ __forceinline__ u64 mul2(u64 a, u64 b) {
    u64 d; asm("mul.rn.f32x2 %0, %1, %2;" : "=l"(d) : "l"(a), "l"(b)); return d;
}

// ---------------- k1: chunk partials (feature-major); block 0 also builds MLP/l tables ----------------
__global__ void k_part(const float* __restrict__ x,
                       const float* __restrict__ wf, const float* __restrict__ q,
                       const float* __restrict__ w1, const float* __restrict__ b1,
                       const float* __restrict__ w2, const float* __restrict__ b2) {
    int t = threadIdx.x;
    int g = blockIdx.x * 128 + t;

    if (blockIdx.x == 0) {   // weight-only prep, runs alongside partials
        __shared__ float stb[HID], sdA[HID], sdB[HID];
        __shared__ float ssA[HID], ssB[HID];
        __shared__ float redA[HID], redB[HID];
        __shared__ float sA0B0[2];

        if (t < HID) {
            float vh = 0.f;
            #pragma unroll
            for (int a = 0; a < 32; a++) vh = fmaf(wf[a], w1[a * HID + t], vh);
            float bh = b1[t], wh = w2[t];
            float tb, dA, dB, cA0 = 0.f, cB0 = 0.f;
            if (vh > 0.f)      { tb = -bh / vh; dA =  wh * vh; dB =  wh * bh; }
            else if (vh < 0.f) { tb = -bh / vh; dA = -wh * vh; dB = -wh * bh;
                                 cA0 = wh * vh; cB0 = wh * bh; }
            else               { tb = 3e38f; dA = 0.f; dB = 0.f;
                                 cB0 = wh * fmaxf(bh, 0.f); }
            stb[t] = tb; sdA[t] = dA; sdB[t] = dB;
            redA[t] = cA0; redB[t] = cB0;
        }
        if (t == 0) {
            float c = 0.f;
            #pragma unroll
            for (int a = 0; a < 32; a++) c = fmaf(wf[a], q[a], c);
            g_kc = c * 1.4426950408889634f;
        }
        if (t < MM) {
            float lf = (float)(t + 1);
            float4 v;
            v.x = 1.0f / lf;
            v.y = lf * (1.0f / 500.0f);
            v.z = logf(lf + 1e-6f) * (1.0f / 6.0f);
            v.w = 0.f;
            g_ltab[t] = v;
        }
        __syncthreads();
        if (t == 0) {
            float A0 = 0.f, B0 = b2[0];
            #pragma unroll
            for (int h = 0; h < HID; h++) { A0 += redA[h]; B0 += redB[h]; }
            sA0B0[0] = A0; sA0B0[1] = B0;
        }
        if (t < HID) {   // stable rank sort + scatter
            float tb = stb[t];
            int rank = 0;
            #pragma unroll
            for (int k = 0; k < HID; k++) {
                float o = stb[k];
                rank += (o < tb) || (o == tb && k < t);
            }
            ssA[rank] = sdA[t]; ssB[rank] = sdB[t];
            g_bp[rank] = tb;
        }
        __syncthreads();
        if (t <= HID) {
            float A = sA0B0[0], B = sA0B0[1];
            for (int k = 0; k < t; k++) { A += ssA[k]; B += ssB[k]; }
            g_ab[t] = make_float2(A, B);
        }
    }

    if (g < NCH * FF) {
        int f = g % FF, ch = g / FF;
        const float* p = x + (size_t)ch * CHROWS * FF + f;
        float s = 0.f, s2 = 0.f;
        #pragma unroll
        for (int r = 0; r < CHROWS; r++) {
            float v = p[r * FF];
            s += v; s2 = fmaf(v, v, s2);
        }
        g_part2[f * NCH + ch] = make_float2(s, s2);
    }
}

// ---------------- k2: warp-per-feature exclusive scan of chunk partials ----------------
__global__ void k_off() {
    int warp = blockIdx.x * 4 + (threadIdx.x >> 5);
    int lane = threadIdx.x & 31;
    if (warp >= FF) return;
    float2* base = g_part2 + warp * NCH + lane * 16;

    float2 loc[16];           // exclusive local prefixes
    float s = 0.f, s2 = 0.f;
    #pragma unroll
    for (int k = 0; k < 16; k++) {
        float2 v = base[k];
        loc[k].x = s; loc[k].y = s2;
        s += v.x; s2 += v.y;
    }
    // inclusive warp scan of lane totals (s, s2)
    float is = s, is2 = s2;
    #pragma unroll
    for (int d = 1; d < 32; d <<= 1) {
        float a = __shfl_up_sync(~0u, is, d);
        float b = __shfl_up_sync(~0u, is2, d);
        if (lane >= d) { is += a; is2 += b; }
    }
    float es = is - s, es2 = is2 - s2;   // exclusive lane offset
    #pragma unroll
    for (int k = 0; k < 16; k++)
        base[k] = make_float2(es + loc[k].x, es2 + loc[k].y);
}

// ---------------- k3: final scan, interleaved output ----------------
__global__ void k_scan(const float* __restrict__ x) {
    int g = blockIdx.x * 128 + threadIdx.x;
    if (g >= NCH * FF) return;
    int f = g % FF, ch = g / FF;

    float2 off = g_part2[f * NCH + ch];
    float s = off.x, s2 = off.y;

    if (ch == 0) ((float2*)g_P)[f] = make_float2(0.f, 0.f);   // row 0
    const float* p = x + (size_t)ch * CHROWS * FF + f;
    float2* o = (float2*)(g_P + ((size_t)ch * CHROWS + 1) * 2 * FF) + f;
    #pragma unroll
    for (int r = 0; r < CHROWS; r++) {
        float v = p[r * FF];
        s += v; s2 = fmaf(v, v, s2);
        o[r * FF] = make_float2(s, s2);
    }
}

// ---------------- k4: main, online softmax, TI=8 -> grid 512 (one full wave @ 4 CTA/SM) ----------------
__global__ __launch_bounds__(256, 4) void k_main(float* __restrict__ out) {
    __shared__ float  sh[ROWS_T * ROWW];
    __shared__ float4 s_lt[MM];
    __shared__ float  s_bp[HID];
    __shared__ float2 s_ab[HID + 1];
    __shared__ float  s_kc;
    int t = threadIdx.x;
    int i0 = blockIdx.x * TI;

    if (t < MM)       s_lt[t] = g_ltab[t];
    if (t < HID)      s_bp[t] = g_bp[t];
    if (t < HID + 1)  s_ab[t] = g_ab[t];
    if (t == 0)       s_kc = g_kc;

    {   // stage tile rows [i0, i0+ROWS_T) of g_P into padded shared rows
        int nrows = min(ROWS_T, LL + 1 - i0);
        int total = nrows * 18;
        const float4* src = (const float4*)(g_P + (size_t)i0 * 2 * FF);
        for (int idx = t; idx < total; idx += 256) {
            int r = idx / 18, c = idx % 18;
            *(float4*)&sh[r * ROWW + c * 4] = src[r * 18 + c];
        }
    }
    __syncthreads();

    float kc = s_kc;
    u64 kc2 = pk(kc, kc);
    const u64 NEG1 = 0xBF800000BF800000ULL;

    #pragma unroll 1
    for (int c = t; c < TI * MM; c += 256) {
        int li  = c / MM;
        int lm1 = c - li * MM;
        int l   = lm1 + 1;
        int gout = i0 * MM + c;
        if (i0 + li + l > LL) { out[gout] = NEG_INF_V; continue; }

        float4 lt  = s_lt[lm1];
        float invl = lt.x, lenf = lt.y, llf = lt.z;

        const float4* pe = (const float4*)&sh[(li + l) * ROWW];
        const float4* pi = (const float4*)&sh[li * ROWW];

        u64 invl2 = pk(invl, invl);

        // online softmax init from the two length features
        float aL = lenf * kc, aG = llf * kc;
        float m = fmaxf(aL, aG);
        u64 den2 = pk(ex2(aL - m), ex2(aG - m));
        u64 num2 = pk(lenf, llf);
        num2 = mul2(num2, den2);

        #pragma unroll
        for (int j = 0; j < 18; j++) {         // 4 features per iteration
            float4 e4 = pe[j], i4 = pi[j];
            u64 elo = pk(e4.x, e4.y), ehi = pk(e4.z, e4.w);
            u64 ilo = pk(i4.x, i4.y), ihi = pk(i4.z, i4.w);
            u64 dlo = fma2(ilo, NEG1, elo);    // (Se-Si, Qe-Qi)
            u64 dhi = fma2(ihi, NEG1, ehi);
            u64 tlo = mul2(dlo, invl2);        // (m, q)
            u64 thi = mul2(dhi, invl2);
            float m0, q0, m1, q1;
            upk(tlo, m0, q0); upk(thi, m1, q1);
            float v0 = fmaf(-m0, m0, q0);
            float v1 = fmaf(-m1, m1, q1);
            u64 ag0 = pk(m0, v0);
            u64 ag1 = pk(m1, v1);
            u64 ar0 = mul2(ag0, kc2);          // args
            u64 ar1 = mul2(ag1, kc2);
            float a0, a1, a2, a3;
            upk(ar0, a0, a1); upk(ar1, a2, a3);
            float mn = fmaxf(fmaxf(m, fmaxf(a0, a1)), fmaxf(a2, a3));
            float sc = ex2(m - mn);
            m = mn;
            u64 ep0 = pk(ex2(a0 - mn), ex2(a1 - mn));
            u64 ep1 = pk(ex2(a2 - mn), ex2(a3 - mn));
            u64 sc2 = pk(sc, sc);
            den2 = fma2(den2, sc2, add2(ep0, ep1));
            num2 = fma2(num2, sc2, fma2(ag0, ep0, mul2(ag1, ep1)));
        }

        float dl, dh, nl, nh;
        upk(den2, dl, dh); upk(num2, nl, nh);
        float s = __fdividef(nl + nh, dl + dh);

        // rank of s among sorted breakpoints (branchless)
        int lo = 0;
        #pragma unroll
        for (int st = 64; st > 0; st >>= 1) {
            int nx = lo + st;
            if (nx <= HID && s >= s_bp[nx - 1]) lo = nx;
        }
        float2 ab = s_ab[lo];
        out[gout] = fmaf(ab.x, s, ab.y);
    }
}

// ---------------- launch ----------------
extern "C" void kernel_launch(void* const* d_in, const int* in_sizes, int n_in,
                              void* d_out, int out_size) {
    const float* x  = (const float*)d_in[0];
    const float* wf = (const float*)d_in[1];
    const float* q  = (const float*)d_in[2];
    const float* w1 = (const float*)d_in[3];
    const float* b1 = (const float*)d_in[4];
    const float* w2 = (const float*)d_in[5];
    const float* b2 = (const float*)d_in[6];
    float* out = (float*)d_out;

    k_part<<<(NCH * FF + 127) / 128, 128>>>(x, wf, q, w1, b1, w2, b2);
    k_off <<<9, 128>>>();
    k_scan<<<(NCH * FF + 127) / 128, 128>>>(x);
    k_main<<<LL / TI, 256>>>(out);
}

// round 11
// speedup vs baseline: 4.2064x; 1.0179x over previous
#include <cuda_runtime.h>
#include <math.h>

#define LL 4096
#define FF 36
#define MM 100
#define HID 64
#define NEG_INF_V (-1e9f)

#define TI 8                     // i-values per k_main block
#define ROWS_T (TI + MM)         // 108 tile rows
#define ROWW 76                  // padded row width in floats (72 data + 4 pad)

typedef unsigned long long u64;

// ---------------- device scratch ----------------
__device__ __align__(128) float g_P[(LL + 1) * 2 * FF];     // interleaved (S, S2)
__device__ float  g_kc;                 // c * log2(e)
__device__ float4 g_ltab[MM];           // (1/l, l/500, log(l+1e-6)/6, 0)
__device__ float  g_bp[HID];            // sorted relu breakpoints
__device__ float2 g_ab[HID + 1];        // (slope, intercept) per bin

// ---------------- f32x2 packed helpers (sm_100) ----------------
__device__ __forceinline__ float ex2(float x) {
    float y; asm("ex2.approx.ftz.f32 %0, %1;" : "=f"(y) : "f"(x)); return y;
}
__device__ __forceinline__ u64 pk(float lo, float hi) {
    u64 r; asm("mov.b64 %0, {%1,%2};" : "=l"(r) : "f"(lo), "f"(hi)); return r;
}
__device__ __forceinline__ void upk(u64 v, float& lo, float& hi) {
    asm("mov.b64 {%0,%1}, %2;" : "=f"(lo), "=f"(hi) : "l"(v));
}
__device__ __forceinline__ u64 fma2(u64 a, u64 b, u64 c) {
    u64 d; asm("fma.rn.f32x2 %0, %1, %2, %3;" : "=l"(d) : "l"(a), "l"(b), "l"(c)); return d;
}
__device__ __forceinline__ u64 add2(u64 a, u64 b) {
    u64 d; asm("add.rn.f32x2 %0, %1, %2;" : "=l"(d) : "l"(a), "l"(b)); return d;
}
__device__ __forceinline__ u64 mul2(u64 a, u64 b) {
    u64 d; asm("mul.rn.f32x2 %0, %1, %2;" : "=l"(d) : "l"(a), "l"(b)); return d;
}

// ---------------- k1: ONE kernel for everything except the cell table ----------------
// blocks 0..35: full prefix scan of feature column f (256 thr x 16 rows, block scan)
// block 36:     weights -> piecewise-linear table + l-tables + kc
__global__ __launch_bounds__(256) void k_scan_all(
        const float* __restrict__ x,
        const float* __restrict__ wf, const float* __restrict__ q,
        const float* __restrict__ w1, const float* __restrict__ b1,
        const float* __restrict__ w2, const float* __restrict__ b2) {
    __shared__ float wS[8], wS2[8];
    __shared__ float stb[HID], sdA[HID], sdB[HID];
    __shared__ float ssA[HID], ssB[HID];
    __shared__ float redA[HID], redB[HID];
    __shared__ float sA0B0[2];
    int t = threadIdx.x;

    if (blockIdx.x == FF) {   // ---- prep block ----
        if (t < HID) {
            float vh = 0.f;
            #pragma unroll
            for (int a = 0; a < 32; a++) vh = fmaf(wf[a], w1[a * HID + t], vh);
            float bh = b1[t], wh = w2[t];
            float tb, dA, dB, cA0 = 0.f, cB0 = 0.f;
            if (vh > 0.f)      { tb = -bh / vh; dA =  wh * vh; dB =  wh * bh; }
            else if (vh < 0.f) { tb = -bh / vh; dA = -wh * vh; dB = -wh * bh;
                                 cA0 = wh * vh; cB0 = wh * bh; }
            else               { tb = 3e38f; dA = 0.f; dB = 0.f;
                                 cB0 = wh * fmaxf(bh, 0.f); }
            stb[t] = tb; sdA[t] = dA; sdB[t] = dB;
            redA[t] = cA0; redB[t] = cB0;
        }
        if (t == 0) {
            float c = 0.f;
            #pragma unroll
            for (int a = 0; a < 32; a++) c = fmaf(wf[a], q[a], c);
            g_kc = c * 1.4426950408889634f;
        }
        if (t < MM) {
            float lf = (float)(t + 1);
            float4 v;
            v.x = 1.0f / lf;
            v.y = lf * (1.0f / 500.0f);
            v.z = logf(lf + 1e-6f) * (1.0f / 6.0f);
            v.w = 0.f;
            g_ltab[t] = v;
        }
        __syncthreads();
        if (t == 0) {
            float A0 = 0.f, B0 = b2[0];
            #pragma unroll
            for (int h = 0; h < HID; h++) { A0 += redA[h]; B0 += redB[h]; }
            sA0B0[0] = A0; sA0B0[1] = B0;
        }
        if (t < HID) {   // stable rank sort + scatter
            float tb = stb[t];
            int rank = 0;
            #pragma unroll
            for (int k = 0; k < HID; k++) {
                float o = stb[k];
                rank += (o < tb) || (o == tb && k < t);
            }
            ssA[rank] = sdA[t]; ssB[rank] = sdB[t];
            g_bp[rank] = tb;
        }
        __syncthreads();
        if (t <= HID) {
            float A = sA0B0[0], B = sA0B0[1];
            for (int k = 0; k < t; k++) { A += ssA[k]; B += ssB[k]; }
            g_ab[t] = make_float2(A, B);
        }
        return;
    }

    // ---- feature-column scan block ----
    int f = blockIdx.x;
    int lane = t & 31, wid = t >> 5;

    float v[16];
    const float* p = x + (size_t)t * 16 * FF + f;
    #pragma unroll
    for (int r = 0; r < 16; r++) v[r] = p[r * FF];

    float ts = 0.f, ts2 = 0.f;
    #pragma unroll
    for (int r = 0; r < 16; r++) { ts += v[r]; ts2 = fmaf(v[r], v[r], ts2); }

    // warp inclusive scan of thread totals
    float is = ts, is2 = ts2;
    #pragma unroll
    for (int d = 1; d < 32; d <<= 1) {
        float a = __shfl_up_sync(~0u, is, d);
        float b = __shfl_up_sync(~0u, is2, d);
        if (lane >= d) { is += a; is2 += b; }
    }
    if (lane == 31) { wS[wid] = is; wS2[wid] = is2; }
    __syncthreads();
    float off = 0.f, off2 = 0.f;
    #pragma unroll
    for (int w = 0; w < 8; w++)
        if (w < wid) { off += wS[w]; off2 += wS2[w]; }
    float s  = off  + is  - ts;    // exclusive prefix for this thread
    float s2 = off2 + is2 - ts2;

    if (t == 0) ((float2*)g_P)[f] = make_float2(0.f, 0.f);   // row 0
    float2* o = (float2*)g_P + f;
    int row0 = t * 16 + 1;
    #pragma unroll
    for (int r = 0; r < 16; r++) {
        float vv = v[r];
        s += vv; s2 = fmaf(vv, vv, s2);
        o[(size_t)(row0 + r) * FF] = make_float2(s, s2);
    }
}

// ---------------- k2: main, grouped online softmax (6 groups x 12 args) ----------------
__global__ __launch_bounds__(256, 4) void k_main(float* __restrict__ out) {
    __shared__ float  sh[ROWS_T * ROWW];
    __shared__ float4 s_lt[MM];
    __shared__ float  s_bp[HID];
    __shared__ float2 s_ab[HID + 1];
    __shared__ float  s_kc;
    int t = threadIdx.x;
    int i0 = blockIdx.x * TI;

    if (t < MM)       s_lt[t] = g_ltab[t];
    if (t < HID)      s_bp[t] = g_bp[t];
    if (t < HID + 1)  s_ab[t] = g_ab[t];
    if (t == 0)       s_kc = g_kc;

    {   // stage tile rows [i0, i0+ROWS_T) of g_P into padded shared rows
        int nrows = min(ROWS_T, LL + 1 - i0);
        int total = nrows * 18;
        const float4* src = (const float4*)(g_P + (size_t)i0 * 2 * FF);
        for (int idx = t; idx < total; idx += 256) {
            int r = idx / 18, c = idx % 18;
            *(float4*)&sh[r * ROWW + c * 4] = src[r * 18 + c];
        }
    }
    __syncthreads();

    float kc = s_kc;
    u64 kc2 = pk(kc, kc);
    const u64 NEG1 = 0xBF800000BF800000ULL;

    #pragma unroll 1
    for (int c = t; c < TI * MM; c += 256) {
        int li  = c / MM;
        int lm1 = c - li * MM;
        int l   = lm1 + 1;
        int gout = i0 * MM + c;
        if (i0 + li + l > LL) { out[gout] = NEG_INF_V; continue; }

        float4 lt  = s_lt[lm1];
        float invl = lt.x, lenf = lt.y, llf = lt.z;

        const float4* pe = (const float4*)&sh[(li + l) * ROWW];
        const float4* pi = (const float4*)&sh[li * ROWW];

        u64 invl2 = pk(invl, invl);

        // online softmax init from the two length features
        float aL = lenf * kc, aG = llf * kc;
        float m = fmaxf(aL, aG);
        u64 den2 = pk(ex2(aL - m), ex2(aG - m));
        u64 num2 = pk(lenf, llf);
        num2 = mul2(num2, den2);

        #pragma unroll
        for (int grp = 0; grp < 6; grp++) {    // 3 float4-pairs = 12 args per group
            u64 ag[6], ar[6];
            #pragma unroll
            for (int k = 0; k < 3; k++) {
                int j = grp * 3 + k;
                float4 e4 = pe[j], i4 = pi[j];
                u64 elo = pk(e4.x, e4.y), ehi = pk(e4.z, e4.w);
                u64 ilo = pk(i4.x, i4.y), ihi = pk(i4.z, i4.w);
                u64 dlo = fma2(ilo, NEG1, elo);    // (Se-Si, Qe-Qi)
                u64 dhi = fma2(ihi, NEG1, ehi);
                u64 tlo = mul2(dlo, invl2);        // (m, q)
                u64 thi = mul2(dhi, invl2);
                float m0, q0, m1, q1;
                upk(tlo, m0, q0); upk(thi, m1, q1);
                float v0 = fmaf(-m0, m0, q0);
                float v1 = fmaf(-m1, m1, q1);
                ag[2 * k]     = pk(m0, v0);
                ag[2 * k + 1] = pk(m1, v1);
                ar[2 * k]     = mul2(ag[2 * k], kc2);
                ar[2 * k + 1] = mul2(ag[2 * k + 1], kc2);
            }
            // local max of 12 args (tree), single rescale
            float a0, a1, a2, a3, a4, a5, a6, a7, a8, a9, aA, aB;
            upk(ar[0], a0, a1); upk(ar[1], a2, a3); upk(ar[2], a4, a5);
            upk(ar[3], a6, a7); upk(ar[4], a8, a9); upk(ar[5], aA, aB);
            float x0 = fmaxf(a0, a1), x1 = fmaxf(a2, a3), x2 = fmaxf(a4, a5);
            float x3 = fmaxf(a6, a7), x4 = fmaxf(a8, a9), x5 = fmaxf(aA, aB);
            x0 = fmaxf(x0, x1); x2 = fmaxf(x2, x3); x4 = fmaxf(x4, x5);
            float lm = fmaxf(fmaxf(x0, x2), x4);
            float mn = fmaxf(m, lm);
            float sc = ex2(m - mn);
            m = mn;
            u64 sc2  = pk(sc, sc);
            u64 nmn2 = pk(-mn, -mn);
            den2 = mul2(den2, sc2);
            num2 = mul2(num2, sc2);
            #pragma unroll
            for (int k = 0; k < 6; k++) {
                u64 shft = add2(ar[k], nmn2);
                float b0, b1; upk(shft, b0, b1);
                u64 ep = pk(ex2(b0), ex2(b1));
                den2 = add2(den2, ep);
                num2 = fma2(ag[k], ep, num2);
            }
        }

        float dl, dh, nl, nh;
        upk(den2, dl, dh); upk(num2, nl, nh);
        float s = __fdividef(nl + nh, dl + dh);

        // rank of s among sorted breakpoints (branchless)
        int lo = 0;
        #pragma unroll
        for (int st = 64; st > 0; st >>= 1) {
            int nx = lo + st;
            if (nx <= HID && s >= s_bp[nx - 1]) lo = nx;
        }
        float2 ab = s_ab[lo];
        out[gout] = fmaf(ab.x, s, ab.y);
    }
}

// ---------------- launch ----------------
extern "C" void kernel_launch(void* const* d_in, const int* in_sizes, int n_in,
                              void* d_out, int out_size) {
    const float* x  = (const float*)d_in[0];
    const float* wf = (const float*)d_in[1];
    const float* q  = (const float*)d_in[2];
    const float* w1 = (const float*)d_in[3];
    const float* b1 = (const float*)d_in[4];
    const float* w2 = (const float*)d_in[5];
    const float* b2 = (const float*)d_in[6];
    float* out = (float*)d_out;

    k_scan_all<<<FF + 1, 256>>>(x, wf, q, w1, b1, w2, b2);
    k_main<<<LL / TI, 256>>>(out);
}